// round 9
// baseline (speedup 1.0000x reference)
#include <cuda_runtime.h>
#include <cuda_bf16.h>

// Plane2Depth: out[b,0,H,W] = 1 / max( s*(p*u + q*v + r), 0.1 )
// [p,q,r,s] = Wmat @ feat[b,:,H/4,W/4];  norm cancels algebraically.
//
// R8: one thread per OUTPUT float4 (4x more warps, 4x shorter chains).
// Block = one output row: grid (768, 16), 192 threads. Thread tid owns
// output cols [4*tid, 4*tid+4) of row oy; its input pixel is
// (h = oy/4, w = tid), v-index j = oy%4. Matvec is recomputed across the
// 4 j-blocks (FMA pipe has huge headroom); MUFU bursts shrink 16 -> 4 per
// thread; store is one contiguous 512B STG.128 per warp-instruction.

#define IN_H   192
#define IN_W   192
#define BATCH  16
#define OUT_HW 768          // 192*4
#define PLANE  (IN_H * IN_W)

__global__ __launch_bounds__(IN_W)
void plane2depth_kernel(const float* __restrict__ feat,
                        const float4* __restrict__ Wmat,
                        float* __restrict__ out)
{
    const int w  = threadIdx.x;       // input column (0..191)
    const int oy = blockIdx.x;        // output row (0..767)
    const int b  = blockIdx.y;        // batch

    const int h = oy >> 2;            // input row
    const int j = oy & 3;             // v index

    // ---- load 4 channels of this pixel (each warp-coalesced 128B, L2-hot) ----
    const float* fp = feat + (size_t)b * 4 * PLANE + (size_t)h * IN_W + w;
    float f0 = fp[0];
    float f1 = fp[PLANE];
    float f2 = fp[2 * PLANE];
    float f3 = fp[3 * PLANE];

    // ---- W matrix: 4 vector loads, uniform broadcast, L1-resident ----
    float4 r0 = __ldg(Wmat + 0);
    float4 r1 = __ldg(Wmat + 1);
    float4 r2 = __ldg(Wmat + 2);
    float4 r3 = __ldg(Wmat + 3);

    float p = fmaf(r0.x, f0, fmaf(r0.y, f1, fmaf(r0.z, f2, r0.w * f3)));
    float q = fmaf(r1.x, f0, fmaf(r1.y, f1, fmaf(r1.z, f2, r1.w * f3)));
    float r = fmaf(r2.x, f0, fmaf(r2.y, f1, fmaf(r2.z, f2, r2.w * f3)));
    float s = fmaf(r3.x, f0, fmaf(r3.y, f1, fmaf(r3.z, f2, r3.w * f3)));

    // fold s:  d = sp*u + (sq*v + sr)
    float sp = s * p;
    float sq = s * q;
    float sr = s * r;

    // v for this output row: ((j) - 1.5) / 4
    float v    = (float)j * 0.25f - 0.375f;
    float base = fmaf(sq, v, sr);

    const float DMIN = 0.1f;   // 1.0 / MAX_DEPTH

    float4 o;
    float d;
    d = fmaf(sp, -0.375f, base); d = fmaxf(d, DMIN); o.x = __fdividef(1.0f, d);
    d = fmaf(sp, -0.125f, base); d = fmaxf(d, DMIN); o.y = __fdividef(1.0f, d);
    d = fmaf(sp,  0.125f, base); d = fmaxf(d, DMIN); o.z = __fdividef(1.0f, d);
    d = fmaf(sp,  0.375f, base); d = fmaxf(d, DMIN); o.w = __fdividef(1.0f, d);

    float* op = out + ((size_t)b * OUT_HW + (size_t)oy) * OUT_HW + (size_t)(4 * w);
    *(float4*)op = o;                 // warp-contiguous 512B
}

extern "C" void kernel_launch(void* const* d_in, const int* in_sizes, int n_in,
                              void* d_out, int out_size)
{
    const float*  feat = (const float*)d_in[0];    // (16,4,192,192) f32
    const float4* Wmat = (const float4*)d_in[1];   // (4,4) f32
    float* out = (float*)d_out;                    // (16,1,768,768) f32

    dim3 grid(OUT_HW, BATCH);    // 768 x 16 = 12288 blocks
    dim3 block(IN_W);            // 192 threads = one output row
    plane2depth_kernel<<<grid, block>>>(feat, Wmat, out);
}